// round 12
// baseline (speedup 1.0000x reference)
#include <cuda_runtime.h>

typedef unsigned long long ull;
#define DI __device__ __forceinline__

DI ull fma2(ull a, ull b, ull c){ ull d; asm("fma.rn.f32x2 %0,%1,%2,%3;" : "=l"(d) : "l"(a),"l"(b),"l"(c)); return d; }
DI ull mul2(ull a, ull b){ ull d; asm("mul.rn.f32x2 %0,%1,%2;" : "=l"(d) : "l"(a),"l"(b)); return d; }
DI ull pk2(float x, float y){ ull r; asm("mov.b64 %0,{%1,%2};" : "=l"(r) : "f"(x),"f"(y)); return r; }
DI float2 up2(ull v){ float2 f; asm("mov.b64 {%0,%1},%2;" : "=f"(f.x),"=f"(f.y) : "l"(v)); return f; }
DI float ex2(float x){ float r; asm("ex2.approx.f32 %0,%1;" : "=f"(r) : "f"(x)); return r; }

static constexpr int L = 2048, D = 1024, M = 8192;

__device__ float g_q[M*D];
__device__ float g_k[M*D];
__device__ float g_v[M*D];
__device__ float g_attn[M*D];

// ---------------------------------------------------------------------------
// GEMM: Y[M,N] = A[M,K] @ W[N,K]^T + bias ; K=N=1024. Tile 128m x 64n, BK=16.
// 256 threads, 8x4 per thread, f32x2 pairs along K (no transpose needed).
// ---------------------------------------------------------------------------
DI int asw(int r, int g){ return r*16 + ((g ^ ((r>>1)&3))<<2); }
DI int wsw(int r, int g){ return r*16 + ((g ^ ((r>>2)&3))<<2); }

DI void gemm_body(const float* __restrict__ A, const float* __restrict__ W,
                  const float* __restrict__ bias, float* __restrict__ Y)
{
    __shared__ __align__(16) float As[128*16];
    __shared__ __align__(16) float Ws[64*16];
    const int tid = threadIdx.x, tx = tid & 15, ty = tid >> 4;
    const int bn = blockIdx.x, bm = blockIdx.y;
    const float* Ap = A + (size_t)(bm*128)*D;
    const float* Wp = W + (size_t)(bn*64)*D;
    const int ar = tid >> 2, ag = tid & 3;   // loader role: row, k-group

    float4 pa0 = *(const float4*)(Ap + (size_t)ar*D      + ag*4);
    float4 pa1 = *(const float4*)(Ap + (size_t)(ar+64)*D + ag*4);
    float4 pw  = *(const float4*)(Wp + (size_t)ar*D      + ag*4);

    ull acc[8][4];
#pragma unroll
    for (int i = 0; i < 8; i++)
#pragma unroll
        for (int j = 0; j < 4; j++) acc[i][j] = 0ull;

    for (int kk = 0; kk < D; kk += 16) {
        __syncthreads();
        *(float4*)&As[asw(ar,    ag)] = pa0;
        *(float4*)&As[asw(ar+64, ag)] = pa1;
        *(float4*)&Ws[wsw(ar,    ag)] = pw;
        __syncthreads();
        if (kk + 16 < D) {   // prefetch next tile while computing
            pa0 = *(const float4*)(Ap + (size_t)ar*D      + kk+16 + ag*4);
            pa1 = *(const float4*)(Ap + (size_t)(ar+64)*D + kk+16 + ag*4);
            pw  = *(const float4*)(Wp + (size_t)ar*D      + kk+16 + ag*4);
        }
#pragma unroll
        for (int g = 0; g < 4; g++) {
            ulonglong2 wv[4];
#pragma unroll
            for (int j = 0; j < 4; j++)
                wv[j] = *(const ulonglong2*)&Ws[wsw(tx*4+j, g)];
#pragma unroll
            for (int i = 0; i < 8; i++) {
                ulonglong2 av = *(const ulonglong2*)&As[asw(ty*8+i, g)];
#pragma unroll
                for (int j = 0; j < 4; j++) {
                    acc[i][j] = fma2(av.x, wv[j].x, acc[i][j]);
                    acc[i][j] = fma2(av.y, wv[j].y, acc[i][j]);
                }
            }
        }
    }

    float4 bv = *(const float4*)(bias + bn*64 + tx*4);
#pragma unroll
    for (int i = 0; i < 8; i++) {
        float2 f0 = up2(acc[i][0]), f1 = up2(acc[i][1]);
        float2 f2 = up2(acc[i][2]), f3 = up2(acc[i][3]);
        float4 o = make_float4(f0.x+f0.y+bv.x, f1.x+f1.y+bv.y,
                               f2.x+f2.y+bv.z, f3.x+f3.y+bv.w);
        *(float4*)(Y + (size_t)(bm*128 + ty*8 + i)*D + bn*64 + tx*4) = o;
    }
}

__global__ __launch_bounds__(256,2)
void qkv_gemm(const float* __restrict__ x,
              const float* __restrict__ Wq, const float* __restrict__ bq,
              const float* __restrict__ Wk, const float* __restrict__ bk,
              const float* __restrict__ Wv, const float* __restrict__ bv)
{
    const float* Wp; const float* bp; float* Yp;
    if (blockIdx.z == 0)      { Wp = Wq; bp = bq; Yp = g_q; }
    else if (blockIdx.z == 1) { Wp = Wk; bp = bk; Yp = g_k; }
    else                      { Wp = Wv; bp = bv; Yp = g_v; }
    gemm_body(x, Wp, bp, Yp);
}

__global__ __launch_bounds__(256,2)
void out_gemm(const float* __restrict__ Wo, const float* __restrict__ bo,
              float* __restrict__ Y)
{
    gemm_body(g_attn, Wo, bo, Y);
}

// ---------------------------------------------------------------------------
// Flash attention: 64x64 Q tile per CTA per (b,h). Online softmax (log2 dom).
// S-loop: f32x2 pairs along d. PV-loop: P duplicated in smem, pairs along d.
// ---------------------------------------------------------------------------
static constexpr int ATTN_SMEM = (4096*3 + 64*132) * 4;  // 82944 B

DI int ksw(int c, int g){ return c*64 + ((g ^ ((c>>2)&7))<<2); }

__global__ __launch_bounds__(256,2) void attn_k()
{
    extern __shared__ __align__(16) float sm[];
    float* Qs = sm;            // [64][64]
    float* Ks = sm + 4096;     // [64][64] swizzled groups
    float* Vs = sm + 8192;     // [64][64]
    float* Ps = sm + 12288;    // [64][132] duplicated pairs

    const int tid = threadIdx.x, tx = tid & 15, ty = tid >> 4;
    const int qt = (int)gridDim.x - 1 - (int)blockIdx.x;  // heavy tiles first
    const int b = blockIdx.y >> 4, h = blockIdx.y & 15;
    const float* qp = g_q + ((size_t)(b*L) + qt*64)*D + h*64;
    const float* kp = g_k + (size_t)(b*L)*D + h*64;
    const float* vp = g_v + (size_t)(b*L)*D + h*64;
    const float QSC = 0.125f * 1.44269504088896340736f;  // hd^-0.5 * log2(e)

#pragma unroll
    for (int t = 0; t < 4; t++) {
        int idx = tid + t*256; int r = idx >> 4; int g = idx & 15;
        float4 q = *(const float4*)(qp + (size_t)r*D + g*4);
        *(float4*)&Qs[r*64 + g*4] = make_float4(q.x*QSC, q.y*QSC, q.z*QSC, q.w*QSC);
    }

    float mi[4], li[4]; ull o2[4][2];
#pragma unroll
    for (int i = 0; i < 4; i++) { mi[i] = -1e30f; li[i] = 0.f; o2[i][0] = 0; o2[i][1] = 0; }
    const int r0 = ty*4, c0 = tx*4;

    for (int kt = 0; kt <= qt; kt++) {
        __syncthreads();
        const float* kb = kp + (size_t)(kt*64)*D;
        const float* vb = vp + (size_t)(kt*64)*D;
#pragma unroll
        for (int t = 0; t < 4; t++) {
            int idx = tid + t*256; int r = idx >> 4; int g = idx & 15;
            *(float4*)&Ks[ksw(r,g)]    = *(const float4*)(kb + (size_t)r*D + g*4);
            *(float4*)&Vs[r*64 + g*4]  = *(const float4*)(vb + (size_t)r*D + g*4);
        }
        __syncthreads();

        // S = (Q*scale*log2e) K^T, pairs along d
        ull s2[4][4];
#pragma unroll
        for (int i = 0; i < 4; i++)
#pragma unroll
            for (int j = 0; j < 4; j++) s2[i][j] = 0ull;
#pragma unroll
        for (int g = 0; g < 16; g++) {
            ulonglong2 kv[4];
#pragma unroll
            for (int j = 0; j < 4; j++)
                kv[j] = *(const ulonglong2*)&Ks[ksw(c0+j, g)];
#pragma unroll
            for (int i = 0; i < 4; i++) {
                ulonglong2 qv = *(const ulonglong2*)&Qs[(r0+i)*64 + g*4];
#pragma unroll
                for (int j = 0; j < 4; j++) {
                    s2[i][j] = fma2(qv.x, kv[j].x, s2[i][j]);
                    s2[i][j] = fma2(qv.y, kv[j].y, s2[i][j]);
                }
            }
        }
        float S[4][4];
#pragma unroll
        for (int i = 0; i < 4; i++)
#pragma unroll
            for (int j = 0; j < 4; j++) { float2 f = up2(s2[i][j]); S[i][j] = f.x + f.y; }
        if (kt == qt) {
#pragma unroll
            for (int i = 0; i < 4; i++)
#pragma unroll
                for (int j = 0; j < 4; j++)
                    if (c0 + j > r0 + i) S[i][j] = -1e30f;
        }
#pragma unroll
        for (int i = 0; i < 4; i++) {
            float mn = fmaxf(fmaxf(S[i][0],S[i][1]), fmaxf(S[i][2],S[i][3]));
            mn = fmaxf(mn, __shfl_xor_sync(0xffffffffu, mn, 1));
            mn = fmaxf(mn, __shfl_xor_sync(0xffffffffu, mn, 2));
            mn = fmaxf(mn, __shfl_xor_sync(0xffffffffu, mn, 4));
            mn = fmaxf(mn, __shfl_xor_sync(0xffffffffu, mn, 8));
            float mnew = fmaxf(mi[i], mn);
            float al = ex2(mi[i] - mnew);
            mi[i] = mnew;
            float p0 = ex2(S[i][0]-mnew), p1 = ex2(S[i][1]-mnew);
            float p2 = ex2(S[i][2]-mnew), p3 = ex2(S[i][3]-mnew);
            li[i] = li[i]*al + ((p0+p1) + (p2+p3));
            ull a2 = pk2(al, al);
            o2[i][0] = mul2(o2[i][0], a2);
            o2[i][1] = mul2(o2[i][1], a2);
            *(float4*)&Ps[(r0+i)*132 + c0*2    ] = make_float4(p0,p0,p1,p1);
            *(float4*)&Ps[(r0+i)*132 + c0*2 + 4] = make_float4(p2,p2,p3,p3);
        }
        __syncthreads();

        // O += P @ V, pairs along d (thread covers d = c0..c0+3)
#pragma unroll 8
        for (int c = 0; c < 64; c += 2) {
            ulonglong2 v0 = *(const ulonglong2*)&Vs[c*64     + c0];
            ulonglong2 v1 = *(const ulonglong2*)&Vs[(c+1)*64 + c0];
#pragma unroll
            for (int i = 0; i < 4; i++) {
                ulonglong2 pp = *(const ulonglong2*)&Ps[(r0+i)*132 + c*2];
                o2[i][0] = fma2(pp.x, v0.x, o2[i][0]);
                o2[i][1] = fma2(pp.x, v0.y, o2[i][1]);
                o2[i][0] = fma2(pp.y, v1.x, o2[i][0]);
                o2[i][1] = fma2(pp.y, v1.y, o2[i][1]);
            }
        }
    }

#pragma unroll
    for (int i = 0; i < 4; i++) {
        float l = li[i];
        l += __shfl_xor_sync(0xffffffffu, l, 1);
        l += __shfl_xor_sync(0xffffffffu, l, 2);
        l += __shfl_xor_sync(0xffffffffu, l, 4);
        l += __shfl_xor_sync(0xffffffffu, l, 8);
        float inv = 1.f / l;
        float2 f0 = up2(o2[i][0]), f1 = up2(o2[i][1]);
        *(float4*)(g_attn + ((size_t)(b*L) + qt*64 + r0 + i)*D + h*64 + c0)
            = make_float4(f0.x*inv, f0.y*inv, f1.x*inv, f1.y*inv);
    }
}

// ---------------------------------------------------------------------------
extern "C" void kernel_launch(void* const* d_in, const int* in_sizes, int n_in,
                              void* d_out, int out_size)
{
    const float* x  = (const float*)d_in[0];
    const float* Wq = (const float*)d_in[1];
    const float* bq = (const float*)d_in[2];
    const float* Wk = (const float*)d_in[3];
    const float* bk = (const float*)d_in[4];
    const float* Wv = (const float*)d_in[5];
    const float* bv = (const float*)d_in[6];
    const float* Wo = (const float*)d_in[7];
    const float* bo = (const float*)d_in[8];
    float* out = (float*)d_out;

    cudaFuncSetAttribute(attn_k, cudaFuncAttributeMaxDynamicSharedMemorySize, ATTN_SMEM);

    qkv_gemm<<<dim3(16, 64, 3), 256>>>(x, Wq, bq, Wk, bk, Wv, bv);
    attn_k<<<dim3(32, 64), 256, ATTN_SMEM>>>();
    out_gemm<<<dim3(16, 64), 256>>>(Wo, bo, out);
}

// round 13
// speedup vs baseline: 1.0030x; 1.0030x over previous
#include <cuda_runtime.h>

typedef unsigned long long ull;
#define DI __device__ __forceinline__

DI ull fma2(ull a, ull b, ull c){ ull d; asm("fma.rn.f32x2 %0,%1,%2,%3;" : "=l"(d) : "l"(a),"l"(b),"l"(c)); return d; }
DI ull mul2(ull a, ull b){ ull d; asm("mul.rn.f32x2 %0,%1,%2;" : "=l"(d) : "l"(a),"l"(b)); return d; }
DI ull pk2(float x, float y){ ull r; asm("mov.b64 %0,{%1,%2};" : "=l"(r) : "f"(x),"f"(y)); return r; }
DI float2 up2(ull v){ float2 f; asm("mov.b64 {%0,%1},%2;" : "=f"(f.x),"=f"(f.y) : "l"(v)); return f; }
DI float ex2(float x){ float r; asm("ex2.approx.f32 %0,%1;" : "=f"(r) : "f"(x)); return r; }

static constexpr int L = 2048, D = 1024, M = 8192;

__device__ float g_q[M*D];
__device__ float g_k[M*D];
__device__ float g_v[M*D];
__device__ float g_attn[M*D];

// ---------------------------------------------------------------------------
// GEMM: Y[M,N] = A[M,K] @ W[N,K]^T + bias ; K=N=1024. Tile 128m x 64n, BK=16.
// 256 threads, 8x4 per thread, f32x2 pairs along K (no transpose needed).
// ---------------------------------------------------------------------------
DI int asw(int r, int g){ return r*16 + ((g ^ ((r>>1)&3))<<2); }
DI int wsw(int r, int g){ return r*16 + ((g ^ ((r>>2)&3))<<2); }

DI void gemm_body(const float* __restrict__ A, const float* __restrict__ W,
                  const float* __restrict__ bias, float* __restrict__ Y)
{
    __shared__ __align__(16) float As[128*16];
    __shared__ __align__(16) float Ws[64*16];
    const int tid = threadIdx.x, tx = tid & 15, ty = tid >> 4;
    const int bn = blockIdx.x, bm = blockIdx.y;
    const float* Ap = A + (size_t)(bm*128)*D;
    const float* Wp = W + (size_t)(bn*64)*D;
    const int ar = tid >> 2, ag = tid & 3;   // loader role: row, k-group

    float4 pa0 = *(const float4*)(Ap + (size_t)ar*D      + ag*4);
    float4 pa1 = *(const float4*)(Ap + (size_t)(ar+64)*D + ag*4);
    float4 pw  = *(const float4*)(Wp + (size_t)ar*D      + ag*4);

    ull acc[8][4];
#pragma unroll
    for (int i = 0; i < 8; i++)
#pragma unroll
        for (int j = 0; j < 4; j++) acc[i][j] = 0ull;

    for (int kk = 0; kk < D; kk += 16) {
        __syncthreads();
        *(float4*)&As[asw(ar,    ag)] = pa0;
        *(float4*)&As[asw(ar+64, ag)] = pa1;
        *(float4*)&Ws[wsw(ar,    ag)] = pw;
        __syncthreads();
        if (kk + 16 < D) {   // prefetch next tile while computing
            pa0 = *(const float4*)(Ap + (size_t)ar*D      + kk+16 + ag*4);
            pa1 = *(const float4*)(Ap + (size_t)(ar+64)*D + kk+16 + ag*4);
            pw  = *(const float4*)(Wp + (size_t)ar*D      + kk+16 + ag*4);
        }
#pragma unroll
        for (int g = 0; g < 4; g++) {
            ulonglong2 wv[4];
#pragma unroll
            for (int j = 0; j < 4; j++)
                wv[j] = *(const ulonglong2*)&Ws[wsw(tx*4+j, g)];
#pragma unroll
            for (int i = 0; i < 8; i++) {
                ulonglong2 av = *(const ulonglong2*)&As[asw(ty*8+i, g)];
#pragma unroll
                for (int j = 0; j < 4; j++) {
                    acc[i][j] = fma2(av.x, wv[j].x, acc[i][j]);
                    acc[i][j] = fma2(av.y, wv[j].y, acc[i][j]);
                }
            }
        }
    }

    float4 bv = *(const float4*)(bias + bn*64 + tx*4);
#pragma unroll
    for (int i = 0; i < 8; i++) {
        float2 f0 = up2(acc[i][0]), f1 = up2(acc[i][1]);
        float2 f2 = up2(acc[i][2]), f3 = up2(acc[i][3]);
        float4 o = make_float4(f0.x+f0.y+bv.x, f1.x+f1.y+bv.y,
                               f2.x+f2.y+bv.z, f3.x+f3.y+bv.w);
        *(float4*)(Y + (size_t)(bm*128 + ty*8 + i)*D + bn*64 + tx*4) = o;
    }
}

__global__ __launch_bounds__(256,2)
void qkv_gemm(const float* __restrict__ x,
              const float* __restrict__ Wq, const float* __restrict__ bq,
              const float* __restrict__ Wk, const float* __restrict__ bk,
              const float* __restrict__ Wv, const float* __restrict__ bv)
{
    const float* Wp; const float* bp; float* Yp;
    if (blockIdx.z == 0)      { Wp = Wq; bp = bq; Yp = g_q; }
    else if (blockIdx.z == 1) { Wp = Wk; bp = bk; Yp = g_k; }
    else                      { Wp = Wv; bp = bv; Yp = g_v; }
    gemm_body(x, Wp, bp, Yp);
}

__global__ __launch_bounds__(256,2)
void out_gemm(const float* __restrict__ Wo, const float* __restrict__ bo,
              float* __restrict__ Y)
{
    gemm_body(g_attn, Wo, bo, Y);
}

// ---------------------------------------------------------------------------
// Flash attention: 64x64 Q tile per CTA per (b,h). Online softmax (log2 dom).
// S-loop: f32x2 pairs along d. PV-loop: P duplicated in smem, pairs along d.
// ---------------------------------------------------------------------------
static constexpr int ATTN_SMEM = (4096*3 + 64*132) * 4;  // 82944 B

DI int ksw(int c, int g){ return c*64 + ((g ^ ((c>>2)&7))<<2); }

__global__ __launch_bounds__(256,2) void attn_k()
{
    extern __shared__ __align__(16) float sm[];
    float* Qs = sm;            // [64][64]
    float* Ks = sm + 4096;     // [64][64] swizzled groups
    float* Vs = sm + 8192;     // [64][64]
    float* Ps = sm + 12288;    // [64][132] duplicated pairs

    const int tid = threadIdx.x, tx = tid & 15, ty = tid >> 4;
    const int qt = (int)gridDim.x - 1 - (int)blockIdx.x;  // heavy tiles first
    const int b = blockIdx.y >> 4, h = blockIdx.y & 15;
    const float* qp = g_q + ((size_t)(b*L) + qt*64)*D + h*64;
    const float* kp = g_k + (size_t)(b*L)*D + h*64;
    const float* vp = g_v + (size_t)(b*L)*D + h*64;
    const float QSC = 0.125f * 1.44269504088896340736f;  // hd^-0.5 * log2(e)

#pragma unroll
    for (int t = 0; t < 4; t++) {
        int idx = tid + t*256; int r = idx >> 4; int g = idx & 15;
        float4 q = *(const float4*)(qp + (size_t)r*D + g*4);
        *(float4*)&Qs[r*64 + g*4] = make_float4(q.x*QSC, q.y*QSC, q.z*QSC, q.w*QSC);
    }

    float mi[4], li[4]; ull o2[4][2];
#pragma unroll
    for (int i = 0; i < 4; i++) { mi[i] = -1e30f; li[i] = 0.f; o2[i][0] = 0; o2[i][1] = 0; }
    const int r0 = ty*4, c0 = tx*4;

    for (int kt = 0; kt <= qt; kt++) {
        __syncthreads();
        const float* kb = kp + (size_t)(kt*64)*D;
        const float* vb = vp + (size_t)(kt*64)*D;
#pragma unroll
        for (int t = 0; t < 4; t++) {
            int idx = tid + t*256; int r = idx >> 4; int g = idx & 15;
            *(float4*)&Ks[ksw(r,g)]    = *(const float4*)(kb + (size_t)r*D + g*4);
            *(float4*)&Vs[r*64 + g*4]  = *(const float4*)(vb + (size_t)r*D + g*4);
        }
        __syncthreads();

        // S = (Q*scale*log2e) K^T, pairs along d
        ull s2[4][4];
#pragma unroll
        for (int i = 0; i < 4; i++)
#pragma unroll
            for (int j = 0; j < 4; j++) s2[i][j] = 0ull;
#pragma unroll
        for (int g = 0; g < 16; g++) {
            ulonglong2 kv[4];
#pragma unroll
            for (int j = 0; j < 4; j++)
                kv[j] = *(const ulonglong2*)&Ks[ksw(c0+j, g)];
#pragma unroll
            for (int i = 0; i < 4; i++) {
                ulonglong2 qv = *(const ulonglong2*)&Qs[(r0+i)*64 + g*4];
#pragma unroll
                for (int j = 0; j < 4; j++) {
                    s2[i][j] = fma2(qv.x, kv[j].x, s2[i][j]);
                    s2[i][j] = fma2(qv.y, kv[j].y, s2[i][j]);
                }
            }
        }
        float S[4][4];
#pragma unroll
        for (int i = 0; i < 4; i++)
#pragma unroll
            for (int j = 0; j < 4; j++) { float2 f = up2(s2[i][j]); S[i][j] = f.x + f.y; }
        if (kt == qt) {
#pragma unroll
            for (int i = 0; i < 4; i++)
#pragma unroll
                for (int j = 0; j < 4; j++)
                    if (c0 + j > r0 + i) S[i][j] = -1e30f;
        }
#pragma unroll
        for (int i = 0; i < 4; i++) {
            float mn = fmaxf(fmaxf(S[i][0],S[i][1]), fmaxf(S[i][2],S[i][3]));
            mn = fmaxf(mn, __shfl_xor_sync(0xffffffffu, mn, 1));
            mn = fmaxf(mn, __shfl_xor_sync(0xffffffffu, mn, 2));
            mn = fmaxf(mn, __shfl_xor_sync(0xffffffffu, mn, 4));
            mn = fmaxf(mn, __shfl_xor_sync(0xffffffffu, mn, 8));
            float mnew = fmaxf(mi[i], mn);
            float al = ex2(mi[i] - mnew);
            mi[i] = mnew;
            float p0 = ex2(S[i][0]-mnew), p1 = ex2(S[i][1]-mnew);
            float p2 = ex2(S[i][2]-mnew), p3 = ex2(S[i][3]-mnew);
            li[i] = li[i]*al + ((p0+p1) + (p2+p3));
            ull a2 = pk2(al, al);
            o2[i][0] = mul2(o2[i][0], a2);
            o2[i][1] = mul2(o2[i][1], a2);
            *(float4*)&Ps[(r0+i)*132 + c0*2    ] = make_float4(p0,p0,p1,p1);
            *(float4*)&Ps[(r0+i)*132 + c0*2 + 4] = make_float4(p2,p2,p3,p3);
        }
        __syncthreads();

        // O += P @ V, pairs along d (thread covers d = c0..c0+3)
#pragma unroll 8
        for (int c = 0; c < 64; c += 2) {
            ulonglong2 v0 = *(const ulonglong2*)&Vs[c*64     + c0];
            ulonglong2 v1 = *(const ulonglong2*)&Vs[(c+1)*64 + c0];
#pragma unroll
            for (int i = 0; i < 4; i++) {
                ulonglong2 pp = *(const ulonglong2*)&Ps[(r0+i)*132 + c*2];
                o2[i][0] = fma2(pp.x, v0.x, o2[i][0]);
                o2[i][1] = fma2(pp.x, v0.y, o2[i][1]);
                o2[i][0] = fma2(pp.y, v1.x, o2[i][0]);
                o2[i][1] = fma2(pp.y, v1.y, o2[i][1]);
            }
        }
    }

#pragma unroll
    for (int i = 0; i < 4; i++) {
        float l = li[i];
        l += __shfl_xor_sync(0xffffffffu, l, 1);
        l += __shfl_xor_sync(0xffffffffu, l, 2);
        l += __shfl_xor_sync(0xffffffffu, l, 4);
        l += __shfl_xor_sync(0xffffffffu, l, 8);
        float inv = 1.f / l;
        float2 f0 = up2(o2[i][0]), f1 = up2(o2[i][1]);
        *(float4*)(g_attn + ((size_t)(b*L) + qt*64 + r0 + i)*D + h*64 + c0)
            = make_float4(f0.x*inv, f0.y*inv, f1.x*inv, f1.y*inv);
    }
}

// ---------------------------------------------------------------------------
extern "C" void kernel_launch(void* const* d_in, const int* in_sizes, int n_in,
                              void* d_out, int out_size)
{
    const float* x  = (const float*)d_in[0];
    const float* Wq = (const float*)d_in[1];
    const float* bq = (const float*)d_in[2];
    const float* Wk = (const float*)d_in[3];
    const float* bk = (const float*)d_in[4];
    const float* Wv = (const float*)d_in[5];
    const float* bv = (const float*)d_in[6];
    const float* Wo = (const float*)d_in[7];
    const float* bo = (const float*)d_in[8];
    float* out = (float*)d_out;

    cudaFuncSetAttribute(attn_k, cudaFuncAttributeMaxDynamicSharedMemorySize, ATTN_SMEM);

    qkv_gemm<<<dim3(16, 64, 3), 256>>>(x, Wq, bq, Wk, bk, Wv, bv);
    attn_k<<<dim3(32, 64), 256, ATTN_SMEM>>>();
    out_gemm<<<dim3(16, 64), 256>>>(Wo, bo, out);
}